// round 3
// baseline (speedup 1.0000x reference)
#include <cuda_runtime.h>
#include <math.h>

#define BB  4
#define NN  4096
#define NGG 4096
#define NUU 8192
#define KK  6

// ---------------- scratch (device globals; no allocation allowed) ----------
__device__ float4 g_ori4[BB*NN];     // normalized ori_pre
__device__ float4 g_norpre4[BB*NN];  // normalized nor_pre
__device__ float4 g_oripro4[BB*NN];  // projected+normalized ori
__device__ float4 g_norgt4[BB*NN];   // gathered gt normals
__device__ unsigned long long g_amin[BB*NN];
__device__ unsigned long long g_knn[BB*NN*2*KK];  // per-split top-6 packed keys
__device__ float g_rm_up_q[BB*NUU];
__device__ float g_rm_up_g[BB*NGG];
__device__ float g_rm_of_q[BB*NUU];
__device__ float g_rm_of_g[BB*NGG];
__device__ double g_acc[4];          // 0: loss_nor sum, 1: loss_nor_ori, 2: smooth

// ---------------- f32x2 helpers (sm_103a packed FMA) ------------------------
__device__ __forceinline__ unsigned long long pk2(float lo, float hi) {
    unsigned long long r;
    asm("mov.b64 %0,{%1,%2};" : "=l"(r) : "f"(lo), "f"(hi));
    return r;
}
__device__ __forceinline__ void upk2(unsigned long long v, float& lo, float& hi) {
    asm("mov.b64 {%0,%1},%2;" : "=f"(lo), "=f"(hi) : "l"(v));
}
__device__ __forceinline__ unsigned long long fma2(unsigned long long a,
                                                   unsigned long long b,
                                                   unsigned long long c) {
    unsigned long long d;
    asm("fma.rn.f32x2 %0,%1,%2,%3;" : "=l"(d) : "l"(a), "l"(b), "l"(c));
    return d;
}
// monotone float->uint mapping (handles negatives), preserves ordering
__device__ __forceinline__ unsigned mono(float f) {
    unsigned u = __float_as_uint(f);
    return u ^ ((unsigned)((int)u >> 31) | 0x80000000u);
}

__device__ __forceinline__ double blockReduceSum(double v) {
    __shared__ double sh[32];
    __syncthreads();
    int lane = threadIdx.x & 31, w = threadIdx.x >> 5;
    #pragma unroll
    for (int o = 16; o; o >>= 1) v += __shfl_down_sync(0xffffffffu, v, o);
    if (lane == 0) sh[w] = v;
    __syncthreads();
    int nw = (blockDim.x + 31) >> 5;
    v = (threadIdx.x < nw) ? sh[threadIdx.x] : 0.0;
    if (w == 0) {
        #pragma unroll
        for (int o = 16; o; o >>= 1) v += __shfl_down_sync(0xffffffffu, v, o);
    }
    return v;
}

// ---------------- setup: init scratch + normalize ---------------------------
__global__ void k_setup(const float* __restrict__ ori, const float* __restrict__ nor) {
    int i = blockIdx.x * blockDim.x + threadIdx.x;
    int stride = gridDim.x * blockDim.x;
    const float INF = __int_as_float(0x7f800000);
    for (int j = i; j < BB*NN; j += stride) g_amin[j] = ~0ull;
    for (int j = i; j < BB*NUU; j += stride) { g_rm_up_q[j] = INF; g_rm_of_q[j] = INF; }
    for (int j = i; j < BB*NGG; j += stride) { g_rm_up_g[j] = INF; g_rm_of_g[j] = INF; }
    if (i < 4) g_acc[i] = 0.0;
    if (i < BB*NN) {
        {
            float x = ori[3*i], y = ori[3*i+1], z = ori[3*i+2];
            float n = sqrtf(x*x + y*y + z*z + 1e-8f) + 1e-10f;
            g_ori4[i] = make_float4(x/n, y/n, z/n, 0.f);
        }
        {
            float x = nor[3*i], y = nor[3*i+1], z = nor[3*i+2];
            float n = sqrtf(x*x + y*y + z*z + 1e-8f) + 1e-10f;
            g_norpre4[i] = make_float4(x/n, y/n, z/n, 0.f);
        }
    }
}

// argmin(pts vs gt.xyz): grid = BB * (NN/512) * 8 = 256 blocks, 256 thr
__global__ void __launch_bounds__(256) k_argmin(const float* __restrict__ pts,
                                                const float* __restrict__ gt) {
    __shared__ float4 s[512];
    const int TS = 8, QCH = NN/512;
    int bx = blockIdx.x;
    int b   = bx / (QCH*TS);
    int rem = bx % (QCH*TS);
    int qc  = rem / TS;
    int tc  = rem % TS;
    int tbase = tc * 512;
    for (int j = threadIdx.x; j < 512; j += 256) {
        const float* gp = gt + (size_t)(b*NGG + tbase + j) * 6;
        float x = gp[0], y = gp[1], z = gp[2];
        s[j] = make_float4(-2.f*x, -2.f*y, -2.f*z, fmaf(x, x, fmaf(y, y, z*z)));
    }
    __syncthreads();
    int q0 = qc*512 + threadIdx.x;
    int q1 = q0 + 256;
    const float* p0 = pts + (size_t)(b*NN + q0) * 3;
    const float* p1 = pts + (size_t)(b*NN + q1) * 3;
    float a0x = p0[0], a0y = p0[1], a0z = p0[2];
    float a1x = p1[0], a1y = p1[1], a1z = p1[2];
    float best0 = 1e30f, best1 = 1e30f;
    int bi0 = 0, bi1 = 0;
    #pragma unroll 4
    for (int j = 0; j < 512; j++) {
        float4 T = s[j];
        float d0 = fmaf(a0x, T.x, fmaf(a0y, T.y, fmaf(a0z, T.z, T.w)));
        float d1 = fmaf(a1x, T.x, fmaf(a1y, T.y, fmaf(a1z, T.z, T.w)));
        if (d0 < best0) { best0 = d0; bi0 = tbase + j; }
        if (d1 < best1) { best1 = d1; bi1 = tbase + j; }
    }
    unsigned long long k0 = ((unsigned long long)mono(best0) << 32) | (unsigned)bi0;
    unsigned long long k1 = ((unsigned long long)mono(best1) << 32) | (unsigned)bi1;
    atomicMin(&g_amin[b*NN + q0], k0);
    atomicMin(&g_amin[b*NN + q1], k1);
}

// per-point: gather normal, projection, loss_nor / loss_nor_ori terms
__global__ void k_post(const float* __restrict__ gt) {
    int i = blockIdx.x * blockDim.x + threadIdx.x;   // 64*256 = 16384 exact
    int b = i / NN;
    unsigned gidx = (unsigned)(g_amin[i] & 0xffffffffu);
    const float* gp = gt + (size_t)(b*NGG + gidx) * 6;
    float gx = gp[3], gy = gp[4], gz = gp[5];
    float4 o = g_ori4[i];
    float dn = fmaf(o.x, gx, fmaf(o.y, gy, o.z*gz));
    float vx = o.x - gx*dn, vy = o.y - gy*dn, vz = o.z - gz*dn;
    float nv = sqrtf(fmaf(vx, vx, fmaf(vy, vy, vz*vz)) + 1e-8f) + 1e-10f;
    g_oripro4[i] = make_float4(vx/nv, vy/nv, vz/nv, 0.f);
    g_norgt4[i]  = make_float4(gx, gy, gz, 0.f);
    float4 p = g_norpre4[i];
    float dpn = fmaf(gx, p.x, fmaf(gy, p.y, gz*p.z));
    float na = fmaxf(sqrtf(fmaf(gx, gx, fmaf(gy, gy, gz*gz))), 1e-8f);
    float nb = fmaxf(sqrtf(fmaf(p.x, p.x, fmaf(p.y, p.y, p.z*p.z))), 1e-8f);
    double t_nor = 1.0 - (double)fabsf(dpn / (na*nb));
    double t_ori = (double)fabsf(dn);
    double s1 = blockReduceSum(t_nor);
    double s2 = blockReduceSum(t_ori);
    if (threadIdx.x == 0) {
        atomicAdd(&g_acc[0], s1);
        atomicAdd(&g_acc[1], s2);
    }
}

// kNN partial top-6 over one target half. grid = BB*(NN/128)*2 = 256 blocks, 128 thr
__global__ void __launch_bounds__(128) k_knn_part(const float* __restrict__ pts) {
    __shared__ float4 s[2048];
    int bx = blockIdx.x;
    int b   = bx / ((NN/128)*2);
    int rem = bx % ((NN/128)*2);
    int qc  = rem / 2;
    int ph  = rem % 2;
    for (int j = threadIdx.x; j < 2048; j += 128) {
        const float* tp = pts + (size_t)(b*NN + ph*2048 + j) * 3;
        float x = tp[0], y = tp[1], z = tp[2];
        s[j] = make_float4(-2.f*x, -2.f*y, -2.f*z, fmaf(x, x, fmaf(y, y, z*z)));
    }
    __syncthreads();
    int qi = qc*128 + threadIdx.x;
    const float* p = pts + (size_t)(b*NN + qi) * 3;
    float ax = p[0], ay = p[1], az = p[2];
    float bd[KK];
    int   bi[KK];
    #pragma unroll
    for (int k = 0; k < KK; k++) { bd[k] = 1e30f; bi[k] = 0; }
    #pragma unroll 4
    for (int j = 0; j < 2048; j++) {
        float4 T = s[j];
        float d = fmaf(ax, T.x, fmaf(ay, T.y, fmaf(az, T.z, T.w)));
        if (d < bd[KK-1]) {
            bd[KK-1] = d; bi[KK-1] = ph*2048 + j;
            #pragma unroll
            for (int k = KK-1; k > 0; k--) {
                if (bd[k] < bd[k-1]) {
                    float td = bd[k]; bd[k] = bd[k-1]; bd[k-1] = td;
                    int   ti = bi[k]; bi[k] = bi[k-1]; bi[k-1] = ti;
                }
            }
        }
    }
    unsigned long long* dst = g_knn + ((size_t)(b*NN + qi) * 2 + ph) * KK;
    #pragma unroll
    for (int k = 0; k < KK; k++)
        dst[k] = ((unsigned long long)mono(bd[k]) << 32) | (unsigned)bi[k];
}

// merge two top-6 lists + smoothness loss. grid 128 x 128
__global__ void k_smooth() {
    int i = blockIdx.x * blockDim.x + threadIdx.x;   // 0..16383
    int b = i / NN;
    unsigned long long a[2*KK];
    const unsigned long long* src = g_knn + (size_t)i * 2 * KK;
    #pragma unroll
    for (int k = 0; k < 2*KK; k++) a[k] = src[k];
    // insertion sort ascending (12 elems)
    #pragma unroll
    for (int k = 1; k < 2*KK; k++) {
        unsigned long long v = a[k];
        int m = k;
        while (m > 0 && a[m-1] > v) { a[m] = a[m-1]; m--; }
        a[m] = v;
    }
    int base = b*NN;
    float4 P = g_oripro4[i];
    float4 G = g_norgt4[i];
    float Rx = P.y*G.z - P.z*G.y;
    float Ry = P.z*G.x - P.x*G.z;
    float Rz = P.x*G.y - P.y*G.x;
    float nP = fmaxf(sqrtf(fmaf(P.x, P.x, fmaf(P.y, P.y, P.z*P.z))), 1e-8f);
    float nR = fmaxf(sqrtf(fmaf(Rx, Rx, fmaf(Ry, Ry, Rz*Rz))), 1e-8f);
    double sum = 0.0;
    #pragma unroll
    for (int k = 0; k < KK; k++) {
        int ni = (int)(unsigned)(a[k] & 0xffffffffu);
        float4 go = g_oripro4[base + ni];
        float4 gn = g_norgt4[base + ni];
        float dnn = fmaf(gn.x, G.x, fmaf(gn.y, G.y, gn.z*G.z));
        float ndv = expf(-dnn / 0.3f) * 10.f + 1.f;
        float w = (ndv < 4.f) ? 1.f : 5.f;
        float ngo = fmaxf(sqrtf(fmaf(go.x, go.x, fmaf(go.y, go.y, go.z*go.z))), 1e-8f);
        float c0 = fmaf(go.x, P.x, fmaf(go.y, P.y, go.z*P.z)) / (ngo*nP);
        float c1 = fmaf(go.x, Rx, fmaf(go.y, Ry, go.z*Rz)) / (ngo*nR);
        float c = fminf(1.f - fabsf(c0), 1.f - fabsf(c1));
        sum += (double)(w * c);
    }
    double tot = blockReduceSum(sum);
    if (threadIdx.x == 0) atomicAdd(&g_acc[2], tot);
}

// chamfer row-min, packed f32x2 inner loop. 256 thr, QPT=8, tile=1024
__global__ void __launch_bounds__(256) k_chamfer(const float* __restrict__ q, int nq, int qs,
                                                 const float* __restrict__ t, int nt, int ts,
                                                 int tsplit, int which) {
    __shared__ ulonglong2 sxy[1024];   // (m2x,m2x) , (m2y,m2y)
    __shared__ ulonglong2 szs[1024];   // (m2z,m2z) , (ss,ss)
    float* rowmin = (which == 0) ? g_rm_up_q :
                    (which == 1) ? g_rm_up_g :
                    (which == 2) ? g_rm_of_q : g_rm_of_g;
    const int QPT = 8;
    int qpb = 256 * QPT;               // 2048 queries per block
    int qch = nq / qpb;
    int bx  = blockIdx.x;
    int b   = bx / (qch * tsplit);
    int rem = bx % (qch * tsplit);
    int qc  = rem / tsplit;
    int tc  = rem % tsplit;
    int tile  = nt / tsplit;           // == 1024 for all call sites
    int tbase = tc * tile;
    for (int j = threadIdx.x; j < tile; j += 256) {
        const float* tp = t + (size_t)(b*nt + tbase + j) * ts;
        float x = tp[0], y = tp[1], z = tp[2];
        float m2x = -2.f*x, m2y = -2.f*y, m2z = -2.f*z;
        float ss = fmaf(x, x, fmaf(y, y, z*z));
        sxy[j] = make_ulonglong2(pk2(m2x, m2x), pk2(m2y, m2y));
        szs[j] = make_ulonglong2(pk2(m2z, m2z), pk2(ss, ss));
    }
    __syncthreads();
    int qbase = qc * qpb;
    float qx[QPT], qy[QPT], qz[QPT], mn[QPT];
    unsigned long long qx2[QPT/2], qy2[QPT/2], qz2[QPT/2];
    #pragma unroll
    for (int l = 0; l < QPT; l++) {
        int qi = qbase + l*256 + threadIdx.x;
        const float* qp = q + (size_t)(b*nq + qi) * qs;
        qx[l] = qp[0]; qy[l] = qp[1]; qz[l] = qp[2];
        mn[l] = 1e30f;
    }
    #pragma unroll
    for (int p = 0; p < QPT/2; p++) {
        qx2[p] = pk2(qx[2*p], qx[2*p+1]);
        qy2[p] = pk2(qy[2*p], qy[2*p+1]);
        qz2[p] = pk2(qz[2*p], qz[2*p+1]);
    }
    #pragma unroll 2
    for (int j = 0; j < tile; j++) {
        ulonglong2 A = sxy[j];
        ulonglong2 B = szs[j];
        #pragma unroll
        for (int p = 0; p < QPT/2; p++) {
            unsigned long long d = fma2(qz2[p], B.x, B.y);
            d = fma2(qy2[p], A.y, d);
            d = fma2(qx2[p], A.x, d);
            float dl, dh;
            upk2(d, dl, dh);
            mn[2*p]   = fminf(mn[2*p],   dl);
            mn[2*p+1] = fminf(mn[2*p+1], dh);
        }
    }
    #pragma unroll
    for (int l = 0; l < QPT; l++) {
        int qi = qbase + l*256 + threadIdx.x;
        float na = fmaf(qx[l], qx[l], fmaf(qy[l], qy[l], qz[l]*qz[l]));
        float v = fmaxf(mn[l] + na, 0.f);
        atomicMin((int*)&rowmin[b*nq + qi], __float_as_int(v));
    }
}

__global__ void k_final(float* __restrict__ out) {
    double s;
    s = 0.0; for (int j = threadIdx.x; j < BB*NUU; j += 256) s += (double)g_rm_up_q[j];
    double up_q = blockReduceSum(s);
    s = 0.0; for (int j = threadIdx.x; j < BB*NGG; j += 256) s += (double)g_rm_up_g[j];
    double up_g = blockReduceSum(s);
    s = 0.0; for (int j = threadIdx.x; j < BB*NUU; j += 256) s += (double)g_rm_of_q[j];
    double of_q = blockReduceSum(s);
    s = 0.0; for (int j = threadIdx.x; j < BB*NGG; j += 256) s += (double)g_rm_of_g[j];
    double of_g = blockReduceSum(s);
    if (threadIdx.x == 0) {
        double loss_nor     = g_acc[0] / (double)(BB*NN);
        double loss_nor_ori = g_acc[1] / (double)(BB*NN);
        double loss_smooth  = g_acc[2] / (double)(BB*NN*KK);
        double lco = of_q / (double)(BB*NUU) + of_g / (double)(BB*NGG);
        double lc  = up_q / (double)(BB*NUU) + up_g / (double)(BB*NGG);
        double loss_cd = lc + 0.4 * lco;
        double loss = loss_smooth + loss_nor + 0.1 * loss_nor_ori + 200.0 * loss_cd;
        out[0] = (float)loss;
        out[1] = (float)loss_smooth;
        out[2] = (float)loss_nor;
        out[3] = (float)lco;
        out[4] = (float)loss_nor_ori;
        out[5] = (float)lc;
        out[6] = (float)lc;
    }
}

// ---------------- launch ----------------------------------------------------
extern "C" void kernel_launch(void* const* d_in, const int* in_sizes, int n_in,
                              void* d_out, int out_size) {
    const float* ori = (const float*)d_in[0];
    const float* nor = (const float*)d_in[1];
    const float* up  = (const float*)d_in[2];
    const float* off = (const float*)d_in[3];
    const float* pts = (const float*)d_in[4];
    const float* gt  = (const float*)d_in[5];
    float* out = (float*)d_out;

    k_setup<<<64, 256>>>(ori, nor);
    k_argmin<<<256, 256>>>(pts, gt);
    k_knn_part<<<256, 128>>>(pts);
    k_post<<<64, 256>>>(gt);
    k_smooth<<<128, 128>>>();
    // up -> gt : nq=8192*? per batch...  (nq=NUU, qch=4, tsplit=4)  4*4*4*? ->
    // grid = B * (nq/2048) * tsplit
    k_chamfer<<<4 * (NUU/2048) * 4, 256>>>(up,  NUU, 3, gt,  NGG, 6, 4, 0); // 256 blocks
    k_chamfer<<<4 * (NGG/2048) * 8, 256>>>(gt,  NGG, 6, up,  NUU, 3, 8, 1); // 256 blocks
    k_chamfer<<<4 * (NUU/2048) * 4, 256>>>(off, NUU, 3, gt,  NGG, 6, 4, 2);
    k_chamfer<<<4 * (NGG/2048) * 8, 256>>>(gt,  NGG, 6, off, NUU, 3, 8, 3);
    k_final<<<1, 256>>>(out);
}

// round 4
// speedup vs baseline: 1.6124x; 1.6124x over previous
#include <cuda_runtime.h>
#include <math.h>

#define BB  4
#define NN  4096
#define NGG 4096
#define NUU 8192
#define KK  6

// ---------------- scratch (device globals; no allocation allowed) ----------
__device__ float4 g_ori4[BB*NN];     // normalized ori_pre
__device__ float4 g_norpre4[BB*NN];  // normalized nor_pre
__device__ float4 g_oripro4[BB*NN];  // projected+normalized ori
__device__ float4 g_norgt4[BB*NN];   // gathered gt normals
__device__ unsigned long long g_amin[BB*NN];
__device__ unsigned long long g_knn[BB*NN*2*KK];  // per-half top-6 packed keys
__device__ float g_rm_up_q[BB*NUU];
__device__ float g_rm_up_g[BB*NGG];
__device__ float g_rm_of_q[BB*NUU];
__device__ float g_rm_of_g[BB*NGG];
__device__ double g_acc[4];          // 0: loss_nor, 1: loss_nor_ori, 2: smooth

// monotone float->uint mapping, preserves ordering incl. negatives
__device__ __forceinline__ unsigned mono(float f) {
    unsigned u = __float_as_uint(f);
    return u ^ ((unsigned)((int)u >> 31) | 0x80000000u);
}

__device__ __forceinline__ double blockReduceSum(double v) {
    __shared__ double sh[32];
    __syncthreads();
    int lane = threadIdx.x & 31, w = threadIdx.x >> 5;
    #pragma unroll
    for (int o = 16; o; o >>= 1) v += __shfl_down_sync(0xffffffffu, v, o);
    if (lane == 0) sh[w] = v;
    __syncthreads();
    int nw = (blockDim.x + 31) >> 5;
    v = (threadIdx.x < nw) ? sh[threadIdx.x] : 0.0;
    if (w == 0) {
        #pragma unroll
        for (int o = 16; o; o >>= 1) v += __shfl_down_sync(0xffffffffu, v, o);
    }
    return v;
}

// ---------------- setup: init scratch + normalize ---------------------------
__global__ void k_setup(const float* __restrict__ ori, const float* __restrict__ nor) {
    int i = blockIdx.x * blockDim.x + threadIdx.x;
    int stride = gridDim.x * blockDim.x;
    const float INF = __int_as_float(0x7f800000);
    for (int j = i; j < BB*NN; j += stride) g_amin[j] = ~0ull;
    for (int j = i; j < BB*NUU; j += stride) { g_rm_up_q[j] = INF; g_rm_of_q[j] = INF; }
    for (int j = i; j < BB*NGG; j += stride) { g_rm_up_g[j] = INF; g_rm_of_g[j] = INF; }
    if (i < 4) g_acc[i] = 0.0;
    if (i < BB*NN) {
        {
            float x = ori[3*i], y = ori[3*i+1], z = ori[3*i+2];
            float n = sqrtf(x*x + y*y + z*z + 1e-8f) + 1e-10f;
            g_ori4[i] = make_float4(x/n, y/n, z/n, 0.f);
        }
        {
            float x = nor[3*i], y = nor[3*i+1], z = nor[3*i+2];
            float n = sqrtf(x*x + y*y + z*z + 1e-8f) + 1e-10f;
            g_norpre4[i] = make_float4(x/n, y/n, z/n, 0.f);
        }
    }
}

// ---------------- fused heavy kernel ----------------------------------------
// blocks [0,128)    : argmin pts vs gt.xyz   (tile 512, QPT=4)
// blocks [128,256)  : knn half-scan          (tile 2048, 1 q/thread)
// blocks [256,384)  : chamfer up  -> gt
// blocks [384,512)  : chamfer gt  -> up
// blocks [512,640)  : chamfer off -> gt
// blocks [640,768)  : chamfer gt  -> off
__device__ __forceinline__ void seg_argmin(const float* __restrict__ pts,
                                           const float* __restrict__ gt,
                                           float4* s, int lbid) {
    const int TS = 8, QCH = 4;                 // 4096 q / (256*4 QPT) = 4 chunks
    int b   = lbid / (QCH*TS);
    int rem = lbid % (QCH*TS);
    int qc  = rem / TS;
    int tc  = rem % TS;
    int tbase = tc * 512;
    for (int j = threadIdx.x; j < 512; j += 256) {
        const float* gp = gt + (size_t)(b*NGG + tbase + j) * 6;
        float x = gp[0], y = gp[1], z = gp[2];
        s[j] = make_float4(-2.f*x, -2.f*y, -2.f*z, fmaf(x, x, fmaf(y, y, z*z)));
    }
    __syncthreads();
    float ax[4], ay[4], az[4], best[4];
    int bi[4];
    int qbase = qc * 1024;
    #pragma unroll
    for (int l = 0; l < 4; l++) {
        int qi = qbase + l*256 + threadIdx.x;
        const float* p = pts + (size_t)(b*NN + qi) * 3;
        ax[l] = p[0]; ay[l] = p[1]; az[l] = p[2];
        best[l] = 1e30f; bi[l] = 0;
    }
    #pragma unroll 2
    for (int j = 0; j < 512; j++) {
        float4 T = s[j];
        #pragma unroll
        for (int l = 0; l < 4; l++) {
            float d = fmaf(ax[l], T.x, fmaf(ay[l], T.y, fmaf(az[l], T.z, T.w)));
            if (d < best[l]) { best[l] = d; bi[l] = tbase + j; }
        }
    }
    #pragma unroll
    for (int l = 0; l < 4; l++) {
        int qi = qbase + l*256 + threadIdx.x;
        unsigned long long k = ((unsigned long long)mono(best[l]) << 32) | (unsigned)bi[l];
        atomicMin(&g_amin[b*NN + qi], k);
    }
}

__device__ __forceinline__ void seg_knn(const float* __restrict__ pts,
                                        float4* s, int lbid) {
    int b   = lbid / 32;
    int rem = lbid % 32;
    int qc  = rem / 2;     // 16 query chunks of 256
    int ph  = rem % 2;     // target half
    for (int j = threadIdx.x; j < 2048; j += 256) {
        const float* tp = pts + (size_t)(b*NN + ph*2048 + j) * 3;
        float x = tp[0], y = tp[1], z = tp[2];
        s[j] = make_float4(-2.f*x, -2.f*y, -2.f*z, fmaf(x, x, fmaf(y, y, z*z)));
    }
    __syncthreads();
    int qi = qc*256 + threadIdx.x;
    const float* p = pts + (size_t)(b*NN + qi) * 3;
    float ax = p[0], ay = p[1], az = p[2];
    float bd[KK];
    int   bi[KK];
    #pragma unroll
    for (int k = 0; k < KK; k++) { bd[k] = 1e30f; bi[k] = 0; }
    #pragma unroll 4
    for (int j = 0; j < 2048; j++) {
        float4 T = s[j];
        float d = fmaf(ax, T.x, fmaf(ay, T.y, fmaf(az, T.z, T.w)));
        if (d < bd[KK-1]) {
            bd[KK-1] = d; bi[KK-1] = ph*2048 + j;
            #pragma unroll
            for (int k = KK-1; k > 0; k--) {
                if (bd[k] < bd[k-1]) {
                    float td = bd[k]; bd[k] = bd[k-1]; bd[k-1] = td;
                    int   ti = bi[k]; bi[k] = bi[k-1]; bi[k-1] = ti;
                }
            }
        }
    }
    unsigned long long* dst = g_knn + ((size_t)(b*NN + qi) * 2 + ph) * KK;
    #pragma unroll
    for (int k = 0; k < KK; k++)
        dst[k] = ((unsigned long long)mono(bd[k]) << 32) | (unsigned)bi[k];
}

__device__ __forceinline__ void seg_chamfer(const float* __restrict__ q, int nq, int qs,
                                            const float* __restrict__ t, int nt, int ts,
                                            int tsplit, float* rowmin,
                                            float4* s, int lbid) {
    const int QPT = 4;
    int qpb = 256 * QPT;                  // 1024 queries / block
    int qch = nq / qpb;
    int b   = lbid / (qch * tsplit);
    int rem = lbid % (qch * tsplit);
    int qc  = rem / tsplit;
    int tc  = rem % tsplit;
    int tile  = nt / tsplit;              // == 1024 at all call sites
    int tbase = tc * tile;
    for (int j = threadIdx.x; j < tile; j += 256) {
        const float* tp = t + (size_t)(b*nt + tbase + j) * ts;
        float x = tp[0], y = tp[1], z = tp[2];
        s[j] = make_float4(-2.f*x, -2.f*y, -2.f*z, fmaf(x, x, fmaf(y, y, z*z)));
    }
    __syncthreads();
    float qx[QPT], qy[QPT], qz[QPT], mn[QPT];
    int qbase = qc * qpb;
    #pragma unroll
    for (int l = 0; l < QPT; l++) {
        int qi = qbase + l*256 + threadIdx.x;
        const float* qp = q + (size_t)(b*nq + qi) * qs;
        qx[l] = qp[0]; qy[l] = qp[1]; qz[l] = qp[2];
        mn[l] = 1e30f;
    }
    #pragma unroll 2
    for (int j = 0; j < tile; j++) {
        float4 T = s[j];
        #pragma unroll
        for (int l = 0; l < QPT; l++) {
            float d = fmaf(qx[l], T.x, fmaf(qy[l], T.y, fmaf(qz[l], T.z, T.w)));
            mn[l] = fminf(mn[l], d);
        }
    }
    #pragma unroll
    for (int l = 0; l < QPT; l++) {
        int qi = qbase + l*256 + threadIdx.x;
        float na = fmaf(qx[l], qx[l], fmaf(qy[l], qy[l], qz[l]*qz[l]));
        float v = fmaxf(mn[l] + na, 0.f);
        atomicMin((int*)&rowmin[b*nq + qi], __float_as_int(v));
    }
}

__global__ void __launch_bounds__(256) k_heavy(const float* __restrict__ pts,
                                               const float* __restrict__ gt,
                                               const float* __restrict__ up,
                                               const float* __restrict__ off) {
    __shared__ float4 s[2048];            // 32 KB, shared by all segments
    int bid = blockIdx.x;
    if (bid < 128) {
        seg_argmin(pts, gt, s, bid);
    } else if (bid < 256) {
        seg_knn(pts, s, bid - 128);
    } else if (bid < 384) {               // up -> gt : qch=8, tsplit=4
        seg_chamfer(up,  NUU, 3, gt,  NGG, 6, 4, g_rm_up_q, s, bid - 256);
    } else if (bid < 512) {               // gt -> up : qch=4, tsplit=8
        seg_chamfer(gt,  NGG, 6, up,  NUU, 3, 8, g_rm_up_g, s, bid - 384);
    } else if (bid < 640) {               // off -> gt
        seg_chamfer(off, NUU, 3, gt,  NGG, 6, 4, g_rm_of_q, s, bid - 512);
    } else {                              // gt -> off
        seg_chamfer(gt,  NGG, 6, off, NUU, 3, 8, g_rm_of_g, s, bid - 640);
    }
}

// per-point: gather normal, projection, loss_nor / loss_nor_ori terms
__global__ void k_post(const float* __restrict__ gt) {
    int i = blockIdx.x * blockDim.x + threadIdx.x;   // 64*256 = 16384 exact
    int b = i / NN;
    unsigned gidx = (unsigned)(g_amin[i] & 0xffffffffu);
    const float* gp = gt + (size_t)(b*NGG + gidx) * 6;
    float gx = gp[3], gy = gp[4], gz = gp[5];
    float4 o = g_ori4[i];
    float dn = fmaf(o.x, gx, fmaf(o.y, gy, o.z*gz));
    float vx = o.x - gx*dn, vy = o.y - gy*dn, vz = o.z - gz*dn;
    float nv = sqrtf(fmaf(vx, vx, fmaf(vy, vy, vz*vz)) + 1e-8f) + 1e-10f;
    g_oripro4[i] = make_float4(vx/nv, vy/nv, vz/nv, 0.f);
    g_norgt4[i]  = make_float4(gx, gy, gz, 0.f);
    float4 p = g_norpre4[i];
    float dpn = fmaf(gx, p.x, fmaf(gy, p.y, gz*p.z));
    float na = fmaxf(sqrtf(fmaf(gx, gx, fmaf(gy, gy, gz*gz))), 1e-8f);
    float nb = fmaxf(sqrtf(fmaf(p.x, p.x, fmaf(p.y, p.y, p.z*p.z))), 1e-8f);
    double t_nor = 1.0 - (double)fabsf(dpn / (na*nb));
    double t_ori = (double)fabsf(dn);
    double s1 = blockReduceSum(t_nor);
    double s2 = blockReduceSum(t_ori);
    if (threadIdx.x == 0) {
        atomicAdd(&g_acc[0], s1);
        atomicAdd(&g_acc[1], s2);
    }
}

// merge two top-6 halves + smoothness loss
__global__ void k_smooth() {
    int i = blockIdx.x * blockDim.x + threadIdx.x;   // 0..16383
    int b = i / NN;
    unsigned long long a[2*KK];
    const unsigned long long* src = g_knn + (size_t)i * 2 * KK;
    #pragma unroll
    for (int k = 0; k < 2*KK; k++) a[k] = src[k];
    #pragma unroll
    for (int k = 1; k < 2*KK; k++) {
        unsigned long long v = a[k];
        int m = k;
        while (m > 0 && a[m-1] > v) { a[m] = a[m-1]; m--; }
        a[m] = v;
    }
    int base = b*NN;
    float4 P = g_oripro4[i];
    float4 G = g_norgt4[i];
    float Rx = P.y*G.z - P.z*G.y;
    float Ry = P.z*G.x - P.x*G.z;
    float Rz = P.x*G.y - P.y*G.x;
    float nP = fmaxf(sqrtf(fmaf(P.x, P.x, fmaf(P.y, P.y, P.z*P.z))), 1e-8f);
    float nR = fmaxf(sqrtf(fmaf(Rx, Rx, fmaf(Ry, Ry, Rz*Rz))), 1e-8f);
    double sum = 0.0;
    #pragma unroll
    for (int k = 0; k < KK; k++) {
        int ni = (int)(unsigned)(a[k] & 0xffffffffu);
        float4 go = g_oripro4[base + ni];
        float4 gn = g_norgt4[base + ni];
        float dnn = fmaf(gn.x, G.x, fmaf(gn.y, G.y, gn.z*G.z));
        float ndv = expf(-dnn / 0.3f) * 10.f + 1.f;
        float w = (ndv < 4.f) ? 1.f : 5.f;
        float ngo = fmaxf(sqrtf(fmaf(go.x, go.x, fmaf(go.y, go.y, go.z*go.z))), 1e-8f);
        float c0 = fmaf(go.x, P.x, fmaf(go.y, P.y, go.z*P.z)) / (ngo*nP);
        float c1 = fmaf(go.x, Rx, fmaf(go.y, Ry, go.z*Rz)) / (ngo*nR);
        float c = fminf(1.f - fabsf(c0), 1.f - fabsf(c1));
        sum += (double)(w * c);
    }
    double tot = blockReduceSum(sum);
    if (threadIdx.x == 0) atomicAdd(&g_acc[2], tot);
}

__global__ void k_final(float* __restrict__ out) {
    double s;
    s = 0.0; for (int j = threadIdx.x; j < BB*NUU; j += 256) s += (double)g_rm_up_q[j];
    double up_q = blockReduceSum(s);
    s = 0.0; for (int j = threadIdx.x; j < BB*NGG; j += 256) s += (double)g_rm_up_g[j];
    double up_g = blockReduceSum(s);
    s = 0.0; for (int j = threadIdx.x; j < BB*NUU; j += 256) s += (double)g_rm_of_q[j];
    double of_q = blockReduceSum(s);
    s = 0.0; for (int j = threadIdx.x; j < BB*NGG; j += 256) s += (double)g_rm_of_g[j];
    double of_g = blockReduceSum(s);
    if (threadIdx.x == 0) {
        double loss_nor     = g_acc[0] / (double)(BB*NN);
        double loss_nor_ori = g_acc[1] / (double)(BB*NN);
        double loss_smooth  = g_acc[2] / (double)(BB*NN*KK);
        double lco = of_q / (double)(BB*NUU) + of_g / (double)(BB*NGG);
        double lc  = up_q / (double)(BB*NUU) + up_g / (double)(BB*NGG);
        double loss_cd = lc + 0.4 * lco;
        double loss = loss_smooth + loss_nor + 0.1 * loss_nor_ori + 200.0 * loss_cd;
        out[0] = (float)loss;
        out[1] = (float)loss_smooth;
        out[2] = (float)loss_nor;
        out[3] = (float)lco;
        out[4] = (float)loss_nor_ori;
        out[5] = (float)lc;
        out[6] = (float)lc;
    }
}

// ---------------- launch ----------------------------------------------------
extern "C" void kernel_launch(void* const* d_in, const int* in_sizes, int n_in,
                              void* d_out, int out_size) {
    const float* ori = (const float*)d_in[0];
    const float* nor = (const float*)d_in[1];
    const float* up  = (const float*)d_in[2];
    const float* off = (const float*)d_in[3];
    const float* pts = (const float*)d_in[4];
    const float* gt  = (const float*)d_in[5];
    float* out = (float*)d_out;

    k_setup<<<64, 256>>>(ori, nor);
    k_heavy<<<768, 256>>>(pts, gt, up, off);
    k_post<<<64, 256>>>(gt);
    k_smooth<<<64, 256>>>();
    k_final<<<1, 256>>>(out);
}

// round 5
// speedup vs baseline: 2.2956x; 1.4238x over previous
#include <cuda_runtime.h>
#include <math.h>

#define BB  4
#define NN  4096
#define NGG 4096
#define NUU 8192
#define KK  6

// ---------------- scratch (device globals; no allocation allowed) ----------
__device__ float4 g_ori4[BB*NN];
__device__ float4 g_norpre4[BB*NN];
__device__ float4 g_oripro4[BB*NN];
__device__ float4 g_norgt4[BB*NN];
__device__ unsigned long long g_amin[BB*NN];
__device__ unsigned long long g_knn[BB*NN*2*KK];
__device__ float g_rm_up_q[BB*NUU];
__device__ float g_rm_up_g[BB*NGG];
__device__ float g_rm_of_q[BB*NUU];
__device__ float g_rm_of_g[BB*NGG];
__device__ double g_acc[8];   // 0 loss_nor, 1 loss_nor_ori, 2 smooth, 3 lc, 4 lco

// ---------------- f32x2 helpers (sm_103a packed FMA) ------------------------
__device__ __forceinline__ unsigned long long pk2(float lo, float hi) {
    unsigned long long r;
    asm("mov.b64 %0,{%1,%2};" : "=l"(r) : "f"(lo), "f"(hi));
    return r;
}
__device__ __forceinline__ void upk2(unsigned long long v, float& lo, float& hi) {
    asm("mov.b64 {%0,%1},%2;" : "=f"(lo), "=f"(hi) : "l"(v));
}
__device__ __forceinline__ unsigned long long fma2(unsigned long long a,
                                                   unsigned long long b,
                                                   unsigned long long c) {
    unsigned long long d;
    asm("fma.rn.f32x2 %0,%1,%2,%3;" : "=l"(d) : "l"(a), "l"(b), "l"(c));
    return d;
}
__device__ __forceinline__ unsigned mono(float f) {
    unsigned u = __float_as_uint(f);
    return u ^ ((unsigned)((int)u >> 31) | 0x80000000u);
}

__device__ __forceinline__ double blockReduceSum(double v) {
    __shared__ double sh[32];
    __syncthreads();
    int lane = threadIdx.x & 31, w = threadIdx.x >> 5;
    #pragma unroll
    for (int o = 16; o; o >>= 1) v += __shfl_down_sync(0xffffffffu, v, o);
    if (lane == 0) sh[w] = v;
    __syncthreads();
    int nw = (blockDim.x + 31) >> 5;
    v = (threadIdx.x < nw) ? sh[threadIdx.x] : 0.0;
    if (w == 0) {
        #pragma unroll
        for (int o = 16; o; o >>= 1) v += __shfl_down_sync(0xffffffffu, v, o);
    }
    return v;
}

// ---------------- setup ------------------------------------------------------
__global__ void k_setup(const float* __restrict__ ori, const float* __restrict__ nor) {
    int i = blockIdx.x * blockDim.x + threadIdx.x;
    int stride = gridDim.x * blockDim.x;
    const float INF = __int_as_float(0x7f800000);
    for (int j = i; j < BB*NN; j += stride) g_amin[j] = ~0ull;
    for (int j = i; j < BB*NUU; j += stride) { g_rm_up_q[j] = INF; g_rm_of_q[j] = INF; }
    for (int j = i; j < BB*NGG; j += stride) { g_rm_up_g[j] = INF; g_rm_of_g[j] = INF; }
    if (i < 8) g_acc[i] = 0.0;
    if (i < BB*NN) {
        {
            float x = ori[3*i], y = ori[3*i+1], z = ori[3*i+2];
            float n = sqrtf(x*x + y*y + z*z + 1e-8f) + 1e-10f;
            g_ori4[i] = make_float4(x/n, y/n, z/n, 0.f);
        }
        {
            float x = nor[3*i], y = nor[3*i+1], z = nor[3*i+2];
            float n = sqrtf(x*x + y*y + z*z + 1e-8f) + 1e-10f;
            g_norpre4[i] = make_float4(x/n, y/n, z/n, 0.f);
        }
    }
}

// ---------------- fused heavy kernel segments -------------------------------
__device__ __forceinline__ void seg_knn(const float* __restrict__ pts,
                                        float4* s, int lbid) {
    int b   = lbid / 32;
    int rem = lbid % 32;
    int qc  = rem / 2;
    int ph  = rem % 2;
    for (int j = threadIdx.x; j < 2048; j += 256) {
        const float* tp = pts + (size_t)(b*NN + ph*2048 + j) * 3;
        float x = tp[0], y = tp[1], z = tp[2];
        s[j] = make_float4(-2.f*x, -2.f*y, -2.f*z, fmaf(x, x, fmaf(y, y, z*z)));
    }
    __syncthreads();
    int qi = qc*256 + threadIdx.x;
    const float* p = pts + (size_t)(b*NN + qi) * 3;
    float ax = p[0], ay = p[1], az = p[2];
    float bd[KK];
    int   bi[KK];
    #pragma unroll
    for (int k = 0; k < KK; k++) { bd[k] = 1e30f; bi[k] = 0; }
    #pragma unroll 4
    for (int j = 0; j < 2048; j++) {
        float4 T = s[j];
        float d = fmaf(ax, T.x, fmaf(ay, T.y, fmaf(az, T.z, T.w)));
        if (d < bd[KK-1]) {
            bd[KK-1] = d; bi[KK-1] = ph*2048 + j;
            #pragma unroll
            for (int k = KK-1; k > 0; k--) {
                if (bd[k] < bd[k-1]) {
                    float td = bd[k]; bd[k] = bd[k-1]; bd[k-1] = td;
                    int   ti = bi[k]; bi[k] = bi[k-1]; bi[k-1] = ti;
                }
            }
        }
    }
    unsigned long long* dst = g_knn + ((size_t)(b*NN + qi) * 2 + ph) * KK;
    #pragma unroll
    for (int k = 0; k < KK; k++)
        dst[k] = ((unsigned long long)mono(bd[k]) << 32) | (unsigned)bi[k];
}

// packed f32x2 chamfer: QPT=8, tile=1024, 256 thr
__device__ __forceinline__ void seg_chamfer(const float* __restrict__ q, int nq, int qs,
                                            const float* __restrict__ t, int nt, int ts,
                                            int tsplit, float* rowmin,
                                            char* smem, int lbid) {
    ulonglong2* sxy = (ulonglong2*)smem;            // (m2x,m2x),(m2y,m2y)
    ulonglong2* szs = (ulonglong2*)(smem + 16384);  // (m2z,m2z),(ss,ss)
    const int QPT = 8;
    int qpb = 256 * QPT;               // 2048 queries / block
    int qch = nq / qpb;
    int b   = lbid / (qch * tsplit);
    int rem = lbid % (qch * tsplit);
    int qc  = rem / tsplit;
    int tc  = rem % tsplit;
    int tile  = nt / tsplit;           // == 1024
    int tbase = tc * tile;
    for (int j = threadIdx.x; j < tile; j += 256) {
        const float* tp = t + (size_t)(b*nt + tbase + j) * ts;
        float x = tp[0], y = tp[1], z = tp[2];
        float m2x = -2.f*x, m2y = -2.f*y, m2z = -2.f*z;
        float ss = fmaf(x, x, fmaf(y, y, z*z));
        sxy[j] = make_ulonglong2(pk2(m2x, m2x), pk2(m2y, m2y));
        szs[j] = make_ulonglong2(pk2(m2z, m2z), pk2(ss, ss));
    }
    __syncthreads();
    int qbase = qc * qpb;
    float qx[QPT], qy[QPT], qz[QPT], mn[QPT];
    unsigned long long qx2[QPT/2], qy2[QPT/2], qz2[QPT/2];
    #pragma unroll
    for (int l = 0; l < QPT; l++) {
        int qi = qbase + l*256 + threadIdx.x;
        const float* qp = q + (size_t)(b*nq + qi) * qs;
        qx[l] = qp[0]; qy[l] = qp[1]; qz[l] = qp[2];
        mn[l] = 1e30f;
    }
    #pragma unroll
    for (int p = 0; p < QPT/2; p++) {
        qx2[p] = pk2(qx[2*p], qx[2*p+1]);
        qy2[p] = pk2(qy[2*p], qy[2*p+1]);
        qz2[p] = pk2(qz[2*p], qz[2*p+1]);
    }
    #pragma unroll 2
    for (int j = 0; j < tile; j++) {
        ulonglong2 A = sxy[j];
        ulonglong2 B = szs[j];
        #pragma unroll
        for (int p = 0; p < QPT/2; p++) {
            unsigned long long d = fma2(qz2[p], B.x, B.y);
            d = fma2(qy2[p], A.y, d);
            d = fma2(qx2[p], A.x, d);
            float dl, dh;
            upk2(d, dl, dh);
            mn[2*p]   = fminf(mn[2*p],   dl);
            mn[2*p+1] = fminf(mn[2*p+1], dh);
        }
    }
    #pragma unroll
    for (int l = 0; l < QPT; l++) {
        int qi = qbase + l*256 + threadIdx.x;
        float na = fmaf(qx[l], qx[l], fmaf(qy[l], qy[l], qz[l]*qz[l]));
        float v = fmaxf(mn[l] + na, 0.f);
        atomicMin((int*)&rowmin[b*nq + qi], __float_as_int(v));
    }
}

__device__ __forceinline__ void seg_argmin(const float* __restrict__ pts,
                                           const float* __restrict__ gt,
                                           float4* s, int lbid) {
    const int TS = 8, QCH = 4;
    int b   = lbid / (QCH*TS);
    int rem = lbid % (QCH*TS);
    int qc  = rem / TS;
    int tc  = rem % TS;
    int tbase = tc * 512;
    for (int j = threadIdx.x; j < 512; j += 256) {
        const float* gp = gt + (size_t)(b*NGG + tbase + j) * 6;
        float x = gp[0], y = gp[1], z = gp[2];
        s[j] = make_float4(-2.f*x, -2.f*y, -2.f*z, fmaf(x, x, fmaf(y, y, z*z)));
    }
    __syncthreads();
    float ax[4], ay[4], az[4], best[4];
    int bi[4];
    int qbase = qc * 1024;
    #pragma unroll
    for (int l = 0; l < 4; l++) {
        int qi = qbase + l*256 + threadIdx.x;
        const float* p = pts + (size_t)(b*NN + qi) * 3;
        ax[l] = p[0]; ay[l] = p[1]; az[l] = p[2];
        best[l] = 1e30f; bi[l] = 0;
    }
    #pragma unroll 2
    for (int j = 0; j < 512; j++) {
        float4 T = s[j];
        #pragma unroll
        for (int l = 0; l < 4; l++) {
            float d = fmaf(ax[l], T.x, fmaf(ay[l], T.y, fmaf(az[l], T.z, T.w)));
            if (d < best[l]) { best[l] = d; bi[l] = tbase + j; }
        }
    }
    #pragma unroll
    for (int l = 0; l < 4; l++) {
        int qi = qbase + l*256 + threadIdx.x;
        unsigned long long k = ((unsigned long long)mono(best[l]) << 32) | (unsigned)bi[l];
        atomicMin(&g_amin[b*NN + qi], k);
    }
}

// blocks [0,128): knn | [128,192): up->gt | [192,256): gt->up
// [256,320): off->gt | [320,384): gt->off | [384,512): argmin
__global__ void __launch_bounds__(256) k_heavy(const float* __restrict__ pts,
                                               const float* __restrict__ gt,
                                               const float* __restrict__ up,
                                               const float* __restrict__ off) {
    __shared__ char smem[32768];
    int bid = blockIdx.x;
    if (bid < 128) {
        seg_knn(pts, (float4*)smem, bid);
    } else if (bid < 192) {   // nq=NUU: qch=4, tsplit=4 -> 4*4*4 = 64
        seg_chamfer(up,  NUU, 3, gt,  NGG, 6, 4, g_rm_up_q, smem, bid - 128);
    } else if (bid < 256) {   // nq=NGG: qch=2, tsplit=8 -> 4*2*8 = 64
        seg_chamfer(gt,  NGG, 6, up,  NUU, 3, 8, g_rm_up_g, smem, bid - 192);
    } else if (bid < 320) {
        seg_chamfer(off, NUU, 3, gt,  NGG, 6, 4, g_rm_of_q, smem, bid - 256);
    } else if (bid < 384) {
        seg_chamfer(gt,  NGG, 6, off, NUU, 3, 8, g_rm_of_g, smem, bid - 320);
    } else {
        seg_argmin(pts, gt, (float4*)smem, bid - 384);
    }
}

// per-point: gather normal, projection, loss_nor / loss_nor_ori terms
__global__ void k_post(const float* __restrict__ gt) {
    int i = blockIdx.x * blockDim.x + threadIdx.x;
    int b = i / NN;
    unsigned gidx = (unsigned)(g_amin[i] & 0xffffffffu);
    const float* gp = gt + (size_t)(b*NGG + gidx) * 6;
    float gx = gp[3], gy = gp[4], gz = gp[5];
    float4 o = g_ori4[i];
    float dn = fmaf(o.x, gx, fmaf(o.y, gy, o.z*gz));
    float vx = o.x - gx*dn, vy = o.y - gy*dn, vz = o.z - gz*dn;
    float nv = sqrtf(fmaf(vx, vx, fmaf(vy, vy, vz*vz)) + 1e-8f) + 1e-10f;
    g_oripro4[i] = make_float4(vx/nv, vy/nv, vz/nv, 0.f);
    g_norgt4[i]  = make_float4(gx, gy, gz, 0.f);
    float4 p = g_norpre4[i];
    float dpn = fmaf(gx, p.x, fmaf(gy, p.y, gz*p.z));
    float na = fmaxf(sqrtf(fmaf(gx, gx, fmaf(gy, gy, gz*gz))), 1e-8f);
    float nb = fmaxf(sqrtf(fmaf(p.x, p.x, fmaf(p.y, p.y, p.z*p.z))), 1e-8f);
    double t_nor = 1.0 - (double)fabsf(dpn / (na*nb));
    double t_ori = (double)fabsf(dn);
    double s1 = blockReduceSum(t_nor);
    double s2 = blockReduceSum(t_ori);
    if (threadIdx.x == 0) {
        atomicAdd(&g_acc[0], s1);
        atomicAdd(&g_acc[1], s2);
    }
}

// blocks [0,64): smoothness; blocks [64,128): weighted rowmin reduction
__global__ void k_smooth() {
    int bid = blockIdx.x;
    if (bid < 64) {
        int i = bid * blockDim.x + threadIdx.x;     // 0..16383
        int b = i / NN;
        unsigned long long a[2*KK];
        const unsigned long long* src = g_knn + (size_t)i * 2 * KK;
        #pragma unroll
        for (int k = 0; k < 2*KK; k++) a[k] = src[k];
        #pragma unroll
        for (int k = 1; k < 2*KK; k++) {
            unsigned long long v = a[k];
            int m = k;
            while (m > 0 && a[m-1] > v) { a[m] = a[m-1]; m--; }
            a[m] = v;
        }
        int base = b*NN;
        float4 P = g_oripro4[i];
        float4 G = g_norgt4[i];
        float Rx = P.y*G.z - P.z*G.y;
        float Ry = P.z*G.x - P.x*G.z;
        float Rz = P.x*G.y - P.y*G.x;
        float nP = fmaxf(sqrtf(fmaf(P.x, P.x, fmaf(P.y, P.y, P.z*P.z))), 1e-8f);
        float nR = fmaxf(sqrtf(fmaf(Rx, Rx, fmaf(Ry, Ry, Rz*Rz))), 1e-8f);
        double sum = 0.0;
        #pragma unroll
        for (int k = 0; k < KK; k++) {
            int ni = (int)(unsigned)(a[k] & 0xffffffffu);
            float4 go = g_oripro4[base + ni];
            float4 gn = g_norgt4[base + ni];
            float dnn = fmaf(gn.x, G.x, fmaf(gn.y, G.y, gn.z*G.z));
            float ndv = expf(-dnn / 0.3f) * 10.f + 1.f;
            float w = (ndv < 4.f) ? 1.f : 5.f;
            float ngo = fmaxf(sqrtf(fmaf(go.x, go.x, fmaf(go.y, go.y, go.z*go.z))), 1e-8f);
            float c0 = fmaf(go.x, P.x, fmaf(go.y, P.y, go.z*P.z)) / (ngo*nP);
            float c1 = fmaf(go.x, Rx, fmaf(go.y, Ry, go.z*Rz)) / (ngo*nR);
            float c = fminf(1.f - fabsf(c0), 1.f - fabsf(c1));
            sum += (double)(w * c);
        }
        double tot = blockReduceSum(sum);
        if (threadIdx.x == 0) atomicAdd(&g_acc[2], tot);
    } else {
        int i = (bid - 64) * blockDim.x + threadIdx.x;   // 0..16383
        const double wq = 1.0 / (double)(BB*NUU);
        const double wg = 1.0 / (double)(BB*NGG);
        double lc = 0.0, lco = 0.0;
        lc  += wq * ((double)g_rm_up_q[i] + (double)g_rm_up_q[i + 16384]);
        lc  += wg * (double)g_rm_up_g[i];
        lco += wq * ((double)g_rm_of_q[i] + (double)g_rm_of_q[i + 16384]);
        lco += wg * (double)g_rm_of_g[i];
        double s1 = blockReduceSum(lc);
        double s2 = blockReduceSum(lco);
        if (threadIdx.x == 0) {
            atomicAdd(&g_acc[3], s1);
            atomicAdd(&g_acc[4], s2);
        }
    }
}

__global__ void k_final(float* __restrict__ out) {
    if (threadIdx.x == 0) {
        double loss_nor     = g_acc[0] / (double)(BB*NN);
        double loss_nor_ori = g_acc[1] / (double)(BB*NN);
        double loss_smooth  = g_acc[2] / (double)(BB*NN*KK);
        double lc  = g_acc[3];
        double lco = g_acc[4];
        double loss_cd = lc + 0.4 * lco;
        double loss = loss_smooth + loss_nor + 0.1 * loss_nor_ori + 200.0 * loss_cd;
        out[0] = (float)loss;
        out[1] = (float)loss_smooth;
        out[2] = (float)loss_nor;
        out[3] = (float)lco;
        out[4] = (float)loss_nor_ori;
        out[5] = (float)lc;
        out[6] = (float)lc;
    }
}

// ---------------- launch ----------------------------------------------------
extern "C" void kernel_launch(void* const* d_in, const int* in_sizes, int n_in,
                              void* d_out, int out_size) {
    const float* ori = (const float*)d_in[0];
    const float* nor = (const float*)d_in[1];
    const float* up  = (const float*)d_in[2];
    const float* off = (const float*)d_in[3];
    const float* pts = (const float*)d_in[4];
    const float* gt  = (const float*)d_in[5];
    float* out = (float*)d_out;

    k_setup<<<64, 256>>>(ori, nor);
    k_heavy<<<512, 256>>>(pts, gt, up, off);
    k_post<<<64, 256>>>(gt);
    k_smooth<<<128, 256>>>();
    k_final<<<1, 32>>>(out);
}